// round 11
// baseline (speedup 1.0000x reference)
#include <cuda_runtime.h>
#include <cstdint>

// Problem constants
#define BB 512
#define VV 32768
#define CC 16
#define TT 128          // threads per block
#define VT (TT / 4)     // 32 v per CTA (4 quad-threads per v)
#define UN 8            // inner unroll

// EMA coefficient: 1 - MOMENTUM = 2/(STEPS_PER_EPOCH+1)
#define ALPHA ((float)(2.0 / 1001.0))

// ---------------------------------------------------------------------------
// Single fused kernel. Thread owns (v, quad q); streams W fully coalesced
// (float4 of channels 4q..4q+3 per sample -> warp reads contiguous 512 B),
// accumulates |sparse*W| into 4 register accumulators (classes 4q..4q+3),
// then applies count / EMA / fresh-copy logic and writes out directly.
// Grid: VV/VT = 1024 CTAs. No partials, no second kernel.
// ---------------------------------------------------------------------------
__global__ void __launch_bounds__(TT)
fused_centroid_kernel(const float* __restrict__ sparse,
                      const float* __restrict__ W,
                      const int* __restrict__ labels,
                      const float* __restrict__ centroids,
                      const int* __restrict__ initialized,
                      float* __restrict__ out)
{
    __shared__ int s_lab[BB];
    __shared__ int s_tot[CC];

    const int tid = threadIdx.x;

    if (tid < CC) s_tot[tid] = 0;
    __syncthreads();
    #pragma unroll
    for (int i = tid; i < BB; i += TT) {
        const int l = labels[i];
        s_lab[i] = l;
        atomicAdd(&s_tot[l], 1);
    }
    __syncthreads();

    const int v = blockIdx.x * VT + (tid >> 2);
    const int q = tid & 3;

    const float* __restrict__ Wp = W + (size_t)v * CC + 4 * q;
    const float* __restrict__ sp = sparse + v;

    float a0 = 0.f, a1 = 0.f, a2 = 0.f, a3 = 0.f;

    for (int b0 = 0; b0 < BB; b0 += UN) {
        float4 w[UN];
        float  sv[UN];
        int    lr[UN];
        bool   sel[UN];

        // Batch global loads for MLP: UN unconditional LDG.128 (W stream)
        // + predicated LDG.32 (sparse, 1-in-4 lanes -> 32B/warp, coalesced).
        #pragma unroll
        for (int j = 0; j < UN; ++j) {
            const int b   = b0 + j;
            const int lab = s_lab[b];
            sel[j] = ((lab >> 2) == q);
            lr[j]  = lab & 3;
            w[j]   = __ldcs(reinterpret_cast<const float4*>(Wp + (size_t)b * VV * CC));
            sv[j]  = 0.f;
            if (sel[j]) sv[j] = __ldcs(sp + (size_t)b * VV);
        }

        #pragma unroll
        for (int j = 0; j < UN; ++j) {
            const int r = lr[j];
            const float ws = (r < 2) ? ((r & 1) ? w[j].y : w[j].x)
                                     : ((r & 1) ? w[j].w : w[j].z);
            const float val = sel[j] ? fabsf(sv[j] * ws) : 0.f;
            a0 += (r == 0) ? val : 0.f;
            a1 += (r == 1) ? val : 0.f;
            a2 += (r == 2) ? val : 0.f;
            a3 += (r == 3) ? val : 0.f;
        }
    }

    // Epilogue: thread finalizes classes 4q..4q+3 at column v.
    float acc[4] = {a0, a1, a2, a3};
    #pragma unroll
    for (int r = 0; r < 4; ++r) {
        const int c = 4 * q + r;
        const int n = s_tot[c];
        const float cen = centroids[(size_t)c * VV + v];
        float o;
        if (n > 0) {
            const float mean = acc[r] / (float)n;
            o = (initialized[c] != 0) ? (cen + ALPHA * (mean - cen)) : mean;
        } else {
            o = cen;
        }
        out[(size_t)c * VV + v] = o;
    }
}

// ---------------------------------------------------------------------------
// Launch: graph-capturable, allocation-free. ONE kernel.
// Inputs identified BY ELEMENT COUNT (robust to metadata ordering):
//   W_eff       f32[B,V,C] -> 268435456 elems
//   sparse_vec  f32[B,V]   ->  16777216 elems
//   centroids   f32[C,V]   ->    524288 elems
//   labels      i32[B]     ->       512 elems
//   initialized i32[C]     ->        16 elems (bool widened to int32)
// Output: f32[C,V].
// ---------------------------------------------------------------------------
extern "C" void kernel_launch(void* const* d_in, const int* in_sizes, int n_in,
                              void* d_out, int out_size)
{
    const float* sparse    = nullptr;
    const float* W         = nullptr;
    const int*   labels    = nullptr;
    const float* centroids = nullptr;
    const int*   init      = nullptr;
    float*       out       = (float*)d_out;

    for (int i = 0; i < n_in; ++i) {
        switch (in_sizes[i]) {
            case BB * VV:            sparse    = (const float*)d_in[i]; break; // 16777216
            case BB:                 labels    = (const int*)d_in[i];   break; // 512
            case CC * VV:            centroids = (const float*)d_in[i]; break; // 524288
            case CC:                 init      = (const int*)d_in[i];   break; // 16
            default:                 W         = (const float*)d_in[i]; break; // 268435456
        }
    }

    fused_centroid_kernel<<<VV / VT, TT>>>(sparse, W, labels, centroids, init, out);
}

// round 12
// speedup vs baseline: 1.1047x; 1.1047x over previous
#include <cuda_runtime.h>
#include <cstdint>

// Problem constants
#define BB 512
#define VV 32768
#define CC 16
#define TT 256          // threads per block
#define HH 2            // B-halves per CTA (intra-CTA split)
#define BH (BB / HH)    // 256 samples per half
#define VT 32           // v per CTA (4 quad-threads x 32 v x 2 halves = 256)
#define UN 4            // inner unroll

// EMA coefficient: 1 - MOMENTUM = 2/(STEPS_PER_EPOCH+1)
#define ALPHA ((float)(2.0 / 1001.0))

// ---------------------------------------------------------------------------
// Single fused kernel, intra-CTA B-split for occupancy.
// Thread = (v, quad q, half h). Streams W fully coalesced (float4 of channels
// 4q..4q+3; warp reads contiguous 512 B), accumulates |sparse*W| into 4
// register accumulators (classes 4q..4q+3) over its 256 samples. h=1 spills
// to smem; h=0 reduces, applies count/EMA/fresh logic, writes out.
// Grid: VV/VT = 1024 CTAs x 8 warps -> ~48-55 warps/SM.
// ---------------------------------------------------------------------------
__global__ void __launch_bounds__(TT)
fused_centroid_kernel(const float* __restrict__ sparse,
                      const float* __restrict__ W,
                      const int* __restrict__ labels,
                      const float* __restrict__ centroids,
                      const int* __restrict__ initialized,
                      float* __restrict__ out)
{
    __shared__ int   s_lab[BB];
    __shared__ int   s_tot[CC];
    __shared__ float s_red[4 * (TT / 2)];   // h=1 accumulators, [r][local]

    const int tid = threadIdx.x;

    if (tid < CC) s_tot[tid] = 0;
    __syncthreads();
    #pragma unroll
    for (int i = tid; i < BB; i += TT) {
        const int l = labels[i];
        s_lab[i] = l;
        atomicAdd(&s_tot[l], 1);
    }
    __syncthreads();

    const int local = tid & 127;          // (v, q) id
    const int h     = tid >> 7;           // B-half
    const int v     = blockIdx.x * VT + (local >> 2);
    const int q     = local & 3;
    const int bbeg  = h * BH;

    const float* __restrict__ Wp = W + (size_t)v * CC + 4 * q;
    const float* __restrict__ sp = sparse + v;

    float a0 = 0.f, a1 = 0.f, a2 = 0.f, a3 = 0.f;

    for (int b0 = bbeg; b0 < bbeg + BH; b0 += UN) {
        float4 w[UN];
        float  sv[UN];
        int    lr[UN];
        bool   sel[UN];

        // Batch global loads for MLP: UN unconditional LDG.128 (W stream)
        // + predicated LDG.32 (sparse, coalesced 32B per warp).
        #pragma unroll
        for (int j = 0; j < UN; ++j) {
            const int b   = b0 + j;
            const int lab = s_lab[b];
            sel[j] = ((lab >> 2) == q);
            lr[j]  = lab & 3;
            w[j]   = __ldcs(reinterpret_cast<const float4*>(Wp + (size_t)b * VV * CC));
            sv[j]  = 0.f;
            if (sel[j]) sv[j] = __ldcs(sp + (size_t)b * VV);
        }

        #pragma unroll
        for (int j = 0; j < UN; ++j) {
            const int r = lr[j];
            const float ws = (r < 2) ? ((r & 1) ? w[j].y : w[j].x)
                                     : ((r & 1) ? w[j].w : w[j].z);
            const float val = sel[j] ? fabsf(sv[j] * ws) : 0.f;
            a0 += (r == 0) ? val : 0.f;
            a1 += (r == 1) ? val : 0.f;
            a2 += (r == 2) ? val : 0.f;
            a3 += (r == 3) ? val : 0.f;
        }
    }

    // Intra-CTA reduction across the two halves (conflict-free: stride-1 in local).
    if (h == 1) {
        s_red[0 * 128 + local] = a0;
        s_red[1 * 128 + local] = a1;
        s_red[2 * 128 + local] = a2;
        s_red[3 * 128 + local] = a3;
    }
    __syncthreads();

    if (h == 0) {
        float acc[4];
        acc[0] = a0 + s_red[0 * 128 + local];
        acc[1] = a1 + s_red[1 * 128 + local];
        acc[2] = a2 + s_red[2 * 128 + local];
        acc[3] = a3 + s_red[3 * 128 + local];

        #pragma unroll
        for (int r = 0; r < 4; ++r) {
            const int c = 4 * q + r;
            const int n = s_tot[c];
            const float cen = centroids[(size_t)c * VV + v];
            float o;
            if (n > 0) {
                const float mean = acc[r] / (float)n;
                o = (initialized[c] != 0) ? (cen + ALPHA * (mean - cen)) : mean;
            } else {
                o = cen;
            }
            out[(size_t)c * VV + v] = o;
        }
    }
}

// ---------------------------------------------------------------------------
// Launch: graph-capturable, allocation-free. ONE kernel.
// Inputs identified BY ELEMENT COUNT (robust to metadata ordering):
//   W_eff       f32[B,V,C] -> 268435456 elems
//   sparse_vec  f32[B,V]   ->  16777216 elems
//   centroids   f32[C,V]   ->    524288 elems
//   labels      i32[B]     ->       512 elems
//   initialized i32[C]     ->        16 elems (bool widened to int32)
// Output: f32[C,V].
// ---------------------------------------------------------------------------
extern "C" void kernel_launch(void* const* d_in, const int* in_sizes, int n_in,
                              void* d_out, int out_size)
{
    const float* sparse    = nullptr;
    const float* W         = nullptr;
    const int*   labels    = nullptr;
    const float* centroids = nullptr;
    const int*   init      = nullptr;
    float*       out       = (float*)d_out;

    for (int i = 0; i < n_in; ++i) {
        switch (in_sizes[i]) {
            case BB * VV:            sparse    = (const float*)d_in[i]; break; // 16777216
            case BB:                 labels    = (const int*)d_in[i];   break; // 512
            case CC * VV:            centroids = (const float*)d_in[i]; break; // 524288
            case CC:                 init      = (const int*)d_in[i];   break; // 16
            default:                 W         = (const float*)d_in[i]; break; // 268435456
        }
    }

    fused_centroid_kernel<<<VV / VT, TT>>>(sparse, W, labels, centroids, init, out);
}